// round 2
// baseline (speedup 1.0000x reference)
#include <cuda_runtime.h>

#define SE 12288           // S*E = 1024*12
#define EPSF 1e-5f

static __device__ float g_attn[1024 * 12];
static __device__ float g_ffn [1024 * 12];

// ---------------------------------------------------------------------------
// attn row for source row 'src' (warp-collective).
// lane k<12: z_k = cos(x[src,k,0]) * cos(rx_k); lanes>=12 hold 1.
// Returns: lane 0 -> prod_{1..11} z ; lane w (1<=w<12) -> prod_{0..w} z.
// ---------------------------------------------------------------------------
__device__ __forceinline__ float attn_row(const float* __restrict__ x,
                                          int src, float crx, int lane)
{
    float z = 1.f;
    if (lane < 12)
        z = cosf(__ldg(&x[(size_t)src * SE + lane * 12])) * crx;
    // inclusive prefix product
    float p = z;
#pragma unroll
    for (int o = 1; o < 16; o <<= 1) {
        float t = __shfl_up_sync(0xffffffffu, p, o);
        if (lane >= o) p *= t;
    }
    // product of z_1..z_11 (exclude lane 0)
    float zz = (lane == 0) ? 1.f : z;
#pragma unroll
    for (int o = 16; o > 0; o >>= 1)
        zz *= __shfl_xor_sync(0xffffffffu, zz, o);
    return (lane == 0) ? zz : p;
}

// ---------------------------------------------------------------------------
// Prep: one warp per b. 128 blocks x 256 threads = 1024 warps.
//   g_attn[b,:], g_ffn[b,:] as in round-1 (same math, warp-parallel).
// ---------------------------------------------------------------------------
__global__ __launch_bounds__(256) void prep_kernel(
    const float* __restrict__ x,
    const float* __restrict__ rx,
    const float* __restrict__ ry,
    const float* __restrict__ w_ffn,
    const float* __restrict__ b_ffn,
    const float* __restrict__ ln1_g,
    const float* __restrict__ ln1_b)
{
    __shared__ float attn_loc[12][12];
    const int warp = threadIdx.x >> 5;   // 0..7
    const int lane = threadIdx.x & 31;
    const int b    = blockIdx.x * 8 + warp;

    const float crx = (lane < 12) ? cosf(__ldg(&rx[lane])) : 1.f;

    // table rows 0..11 (attn for seq positions < 12), shared per block
    {
        float a = attn_row(x, warp, crx, lane);          // rows 0..7
        if (lane < 12) attn_loc[warp][lane] = a;
        if (warp < 4) {
            float a2 = attn_row(x, 8 + warp, crx, lane); // rows 8..11
            if (lane < 12) attn_loc[8 + warp][lane] = a2;
        }
    }
    __syncthreads();

    // attn for own b
    {
        float a = attn_row(x, b, crx, lane);
        if (lane < 12) g_attn[b * 12 + lane] = a;
    }

    // ffn for own b: lane i<12 computes r_i = relu(cos(tok2_i + ry_i))
    const float g10 = __ldg(&ln1_g[0]);
    const float b10 = __ldg(&ln1_b[0]);
    float r = 0.f;
    if (lane < 12) {
        const float4* row = (const float4*)(x + (size_t)b * SE + lane * 12);
        float4 a0 = __ldg(row), a1 = __ldg(row + 1), a2 = __ldg(row + 2);
        float y[12] = {a0.x, a0.y, a0.z, a0.w,
                       a1.x, a1.y, a1.z, a1.w,
                       a2.x, a2.y, a2.z, a2.w};
        float sum = 0.f;
#pragma unroll
        for (int e = 0; e < 12; e++) { y[e] += attn_loc[lane][e]; sum += y[e]; }
        const float mu = sum * (1.f / 12.f);
        float sq = 0.f;
#pragma unroll
        for (int e = 0; e < 12; e++) { const float d = y[e] - mu; sq += d * d; }
        const float rs  = rsqrtf(sq * (1.f / 12.f) + EPSF);
        const float x10 = (y[0] - mu) * rs * g10 + b10;
        r = fmaxf(cosf(x10 + __ldg(&ry[lane])), 0.f);
    }

    // matvec: lane e<12 accumulates ffn[e]
    float wrow[12];
    if (lane < 12) {
#pragma unroll
        for (int i = 0; i < 12; i++) wrow[i] = __ldg(&w_ffn[lane * 12 + i]);
    }
    float acc = (lane < 12) ? __ldg(&b_ffn[lane]) : 0.f;
#pragma unroll
    for (int i = 0; i < 12; i++) {
        const float ri = __shfl_sync(0xffffffffu, r, i);
        acc = fmaf(ri, wrow[i], acc);
    }
    if (lane < 12) g_ffn[b * 12 + lane] = acc;
}

// ---------------------------------------------------------------------------
// Main: out[b,s,:] = LN2( LN1(x[b,s,:] + attn[s,:]) + ffn[s,:] )
// Block = 256 threads, tile = 64 s x 16 b; thread = (s_idx, b_grp) x 4 rows.
// All per-s / per-e tables live in SHARED (pad-13 -> conflict-free), keeping
// regs <= 42 for high occupancy. x / out touched once -> streaming hints.
// ---------------------------------------------------------------------------
__global__ __launch_bounds__(256, 6) void main_kernel(
    const float* __restrict__ x, float* __restrict__ out,
    const float* __restrict__ ln1_g, const float* __restrict__ ln1_b,
    const float* __restrict__ ln2_g, const float* __restrict__ ln2_b)
{
    __shared__ float attn_sh[64][13];
    __shared__ float c1_sh[64][13];
    __shared__ float g1s[12], g2s[12], b2s[12];

    const int tid = threadIdx.x;
    const int s0  = blockIdx.x * 64;

    for (int idx = tid; idx < 768; idx += 256) {
        const int r = idx / 12, e = idx - r * 12;
        attn_sh[r][e] = g_attn[(s0 + r) * 12 + e];
        c1_sh[r][e]   = __ldg(&ln1_b[e]) + g_ffn[(s0 + r) * 12 + e];
    }
    if (tid < 12) {
        g1s[tid] = __ldg(&ln1_g[tid]);
        g2s[tid] = __ldg(&ln2_g[tid]);
        b2s[tid] = __ldg(&ln2_b[tid]);
    }
    __syncthreads();

    const int s_idx = tid & 63;
    const int b_grp = tid >> 6;                       // 0..3
    const int s     = s0 + s_idx;
    const int b0    = blockIdx.y * 16 + b_grp * 4;

#pragma unroll
    for (int bi = 0; bi < 4; bi++) {
        const size_t off = ((size_t)(b0 + bi) * 1024 + (size_t)s) * 12;
        const float4* row = (const float4*)(x + off);
        float4 a0 = __ldcs(row), a1 = __ldcs(row + 1), a2 = __ldcs(row + 2);
        float y[12] = {a0.x, a0.y, a0.z, a0.w,
                       a1.x, a1.y, a1.z, a1.w,
                       a2.x, a2.y, a2.z, a2.w};
        float sum = 0.f;
#pragma unroll
        for (int e = 0; e < 12; e++) { y[e] += attn_sh[s_idx][e]; sum += y[e]; }
        const float mu = sum * (1.f / 12.f);
        float sq = 0.f;
#pragma unroll
        for (int e = 0; e < 12; e++) { const float d = y[e] - mu; sq += d * d; }
        const float rs1 = rsqrtf(sq * (1.f / 12.f) + EPSF);

        float y2[12];
        float sum2 = 0.f;
#pragma unroll
        for (int e = 0; e < 12; e++) {
            y2[e] = (y[e] - mu) * rs1 * g1s[e] + c1_sh[s_idx][e];
            sum2 += y2[e];
        }
        const float mu2 = sum2 * (1.f / 12.f);
        float sq2 = 0.f;
#pragma unroll
        for (int e = 0; e < 12; e++) { const float d = y2[e] - mu2; sq2 += d * d; }
        const float rs2 = rsqrtf(sq2 * (1.f / 12.f) + EPSF);

        float o[12];
#pragma unroll
        for (int e = 0; e < 12; e++)
            o[e] = (y2[e] - mu2) * rs2 * g2s[e] + b2s[e];

        float4* orow = (float4*)(out + off);
        __stcs(orow,     make_float4(o[0], o[1], o[2],  o[3]));
        __stcs(orow + 1, make_float4(o[4], o[5], o[6],  o[7]));
        __stcs(orow + 2, make_float4(o[8], o[9], o[10], o[11]));
    }
}

extern "C" void kernel_launch(void* const* d_in, const int* in_sizes, int n_in,
                              void* d_out, int out_size)
{
    const float* x     = (const float*)d_in[0];
    const float* rx    = (const float*)d_in[1];
    const float* ry    = (const float*)d_in[2];
    const float* w_ffn = (const float*)d_in[3];
    const float* b_ffn = (const float*)d_in[4];
    const float* ln1_g = (const float*)d_in[5];
    const float* ln1_b = (const float*)d_in[6];
    const float* ln2_g = (const float*)d_in[7];
    const float* ln2_b = (const float*)d_in[8];
    float* out = (float*)d_out;

    prep_kernel<<<128, 256>>>(x, rx, ry, w_ffn, b_ffn, ln1_g, ln1_b);

    dim3 grid(16, 64);   // 1024 blocks: 64 s x 16 b tiles
    main_kernel<<<grid, 256>>>(x, out, ln1_g, ln1_b, ln2_g, ln2_b);
}